// round 2
// baseline (speedup 1.0000x reference)
#include <cuda_runtime.h>
#include <cuda_bf16.h>
#include <math.h>

#define TT 128
#define BB 256
#define DD 128
#define LL 32
#define CC 64
#define HH 256
#define SS 16
#define SB 4096   // SS*BB

#define DTV 0.02f
#define SQDT 0.14142135623730951f     // sqrt(0.02)
#define LOGDT -3.9120230054281460f    // log(0.02)

// ---------------- device scratch (static allocations only) ----------------
static __device__ float g_WihT[DD*768];
static __device__ float g_WhhT[HH*768];
static __device__ float g_fW1t[96*HH];
static __device__ float g_fW2t[HH*HH];
static __device__ float g_fW3t[HH*LL];
static __device__ float g_hW1t[LL*HH];
static __device__ float g_hW2t[HH*HH];
static __device__ float g_hW3t[HH*LL];
static __device__ float g_encWt[HH*CC];
static __device__ float g_gi[TT*BB*768];      // precomputed input gates (reversed time)
static __device__ float g_h[BB*HH];           // GRU hidden
static __device__ float g_hs[TT*BB*HH];       // all hidden states (reversed time)
static __device__ float g_ctx[TT*BB*CC];      // context, forward time (flip applied)
static __device__ float g_logqp[SB];          // per-(s,b) path logqp accumulator
static __device__ double g_acc[2];            // [0]=sum ell, [1]=sum kl0

__device__ __forceinline__ float sigm_(float x){ return 1.f/(1.f+__expf(-x)); }
__device__ __forceinline__ float splus_(float x){
    return fmaxf(x,0.f) + __logf(1.f+__expf(-fabsf(x)));
}

// ---------------- prep: zero state + transpose weights ----------------
__global__ void prep_kernel(const float* __restrict__ Wih, const float* __restrict__ Whh,
                            const float* __restrict__ fW1, const float* __restrict__ fW2,
                            const float* __restrict__ fW3, const float* __restrict__ hW1,
                            const float* __restrict__ hW2, const float* __restrict__ hW3,
                            const float* __restrict__ encW){
    int i = blockIdx.x*blockDim.x + threadIdx.x;
    int nth = gridDim.x*blockDim.x;
    for (int k=i;k<BB*HH;k+=nth) g_h[k]=0.f;
    for (int k=i;k<SB;k+=nth)    g_logqp[k]=0.f;
    if (i<2) g_acc[i]=0.0;
    for (int k=i;k<768*DD;k+=nth){int n=k/DD,d=k%DD; g_WihT[d*768+n]=Wih[k];}
    for (int k=i;k<768*HH;k+=nth){int n=k/HH,d=k%HH; g_WhhT[d*768+n]=Whh[k];}
    for (int k=i;k<HH*96;k+=nth){int h=k/96,c=k%96;  g_fW1t[c*HH+h]=fW1[k];}
    for (int k=i;k<HH*HH;k+=nth){int h=k/HH,c=k%HH;  g_fW2t[c*HH+h]=fW2[k];}
    for (int k=i;k<LL*HH;k+=nth){int l=k/HH,c=k%HH;  g_fW3t[c*LL+l]=fW3[k];}
    for (int k=i;k<HH*LL;k+=nth){int h=k/LL,c=k%LL;  g_hW1t[c*HH+h]=hW1[k];}
    for (int k=i;k<HH*HH;k+=nth){int h=k/HH,c=k%HH;  g_hW2t[c*HH+h]=hW2[k];}
    for (int k=i;k<LL*HH;k+=nth){int l=k/HH,c=k%HH;  g_hW3t[c*LL+l]=hW3[k];}
    for (int k=i;k<CC*HH;k+=nth){int c2=k/HH,kk=k%HH;g_encWt[kk*CC+c2]=encW[k];}
}

// ---------------- gi = xs_rev @ WihT + bih  (one big GEMM) ----------------
__global__ void gi_kernel(const float* __restrict__ xs_pre, const float* __restrict__ bih){
    __shared__ float xT[DD*8];   // [k][i]
    int tid = threadIdx.x;       // 256
    int row0 = blockIdx.x*8;     // 4096 blocks
    for (int e=tid; e<8*DD; e+=256){
        int i=e>>7, k=e&127;
        int rid=row0+i; int t=rid>>8, b=rid&255;
        xT[k*8+i] = xs_pre[(b*TT + (TT-1-t))*DD + k];
    }
    __syncthreads();
    int n0=tid, n1=tid+256, n2=tid+512;
    float a0[8],a1[8],a2[8];
    float b0=bih[n0], b1=bih[n1], b2=bih[n2];
    #pragma unroll
    for(int i=0;i<8;i++){a0[i]=b0;a1[i]=b1;a2[i]=b2;}
    #pragma unroll 2
    for(int k=0;k<DD;k++){
        float w0=g_WihT[k*768+n0], w1=g_WihT[k*768+n1], w2=g_WihT[k*768+n2];
        float4 xa=*(const float4*)&xT[k*8], xb=*(const float4*)&xT[k*8+4];
        float xv[8]={xa.x,xa.y,xa.z,xa.w,xb.x,xb.y,xb.z,xb.w};
        #pragma unroll
        for(int i=0;i<8;i++){a0[i]=fmaf(xv[i],w0,a0[i]);a1[i]=fmaf(xv[i],w1,a1[i]);a2[i]=fmaf(xv[i],w2,a2[i]);}
    }
    for(int i=0;i<8;i++){
        int rid=row0+i;
        g_gi[rid*768+n0]=a0[i]; g_gi[rid*768+n1]=a1[i]; g_gi[rid*768+n2]=a2[i];
    }
}

// ---------------- one GRU step (fused GEMM + gates) ----------------
__global__ void gru_step_kernel(int t, const float* __restrict__ bhh){
    __shared__ float hT[HH*4];   // [k][i]
    int tid = threadIdx.x;       // 128
    int h = blockIdx.y*128 + tid;
    int b0 = blockIdx.x*4;       // grid (64,2)
    for(int e=tid;e<4*HH;e+=128){ int i=e>>8, k=e&255; hT[k*4+i]=g_h[(b0+i)*HH+k]; }
    __syncthreads();
    float ar[4],az[4],an[4];
    float br=bhh[h], bz=bhh[256+h], bn=bhh[512+h];
    #pragma unroll
    for(int i=0;i<4;i++){ar[i]=br;az[i]=bz;an[i]=bn;}
    #pragma unroll 4
    for(int k=0;k<HH;k++){
        float wr=g_WhhT[k*768+h], wz=g_WhhT[k*768+256+h], wn=g_WhhT[k*768+512+h];
        float4 hv=*(const float4*)&hT[k*4];
        float hvv[4]={hv.x,hv.y,hv.z,hv.w};
        #pragma unroll
        for(int i=0;i<4;i++){ar[i]=fmaf(hvv[i],wr,ar[i]);az[i]=fmaf(hvv[i],wz,az[i]);an[i]=fmaf(hvv[i],wn,an[i]);}
    }
    #pragma unroll
    for(int i=0;i<4;i++){
        int b=b0+i;
        long base=(long)(t*BB+b)*768;
        float gr=g_gi[base+h], gz=g_gi[base+256+h], gn=g_gi[base+512+h];
        float r = sigm_(gr+ar[i]);
        float u = sigm_(gz+az[i]);
        float nn = tanhf(gn + r*an[i]);
        float hp = hT[h*4+i];
        float hnw = (1.f-u)*nn + u*hp;
        g_h[b*HH+h]=hnw;
        g_hs[(t*BB+b)*HH+h]=hnw;
    }
}

// ---------------- ctx = hs @ encWt + enc_b, flipped to forward time ----------------
__global__ void ctx_kernel(const float* __restrict__ enc_b){
    __shared__ float hT[HH*4];
    int tid=threadIdx.x;             // 256
    int row0=blockIdx.x*4;           // 8192 blocks
    for(int e=tid;e<4*HH;e+=256){int i=e>>8,k=e&255; hT[k*4+i]=g_hs[(row0+i)*HH+k];}
    __syncthreads();
    int i=tid>>6, c=tid&63;
    float acc=enc_b[c];
    #pragma unroll 4
    for(int k=0;k<HH;k++) acc = fmaf(hT[k*4+i], g_encWt[k*CC+c], acc);
    int rid=row0+i; int tr=rid>>8, b=rid&255;
    g_ctx[((TT-1-tr)*BB + b)*CC + c] = acc;
}

// ---------------- z0 + KL(q||p) ----------------
__global__ void z0_kernel(const float* __restrict__ eps0, const float* __restrict__ qz0_W,
                          const float* __restrict__ qz0_b, const float* __restrict__ pz0_mean,
                          const float* __restrict__ pz0_logstd, float* __restrict__ out){
    int b = blockIdx.x;      // 256
    int tid = threadIdx.x;   // 64
    __shared__ float c0[64]; __shared__ float q[64];
    c0[tid] = g_ctx[b*CC + tid];   // ctx[0][b][c]
    __syncthreads();
    float acc = qz0_b[tid];
    for(int c=0;c<CC;c++) acc = fmaf(c0[c], qz0_W[tid*CC+c], acc);
    q[tid]=acc;
    __syncthreads();
    if(tid<32){
        float qm=q[tid], ql=q[32+tid];
        float pm=pz0_mean[tid], pl=pz0_logstd[tid];
        float kl = pl - ql + (expf(2.f*ql) + (qm-pm)*(qm-pm))/(2.f*expf(2.f*pl)) - 0.5f;
        #pragma unroll
        for(int off=16;off;off>>=1) kl += __shfl_down_sync(0xffffffffu, kl, off);
        if(tid==0) atomicAdd(&g_acc[1], (double)kl);
    }
    float* zs = out+1;
    for(int e=tid;e<SS*LL;e+=64){
        int s=e>>5, l=e&31;
        float val = q[l] + expf(q[32+l]) * eps0[(s*BB+b)*LL + l];
        zs[((long)(s*BB+b)*TT + 0)*LL + l] = val;
    }
}

// ---------------- fused MLP layer helpers (column-parallel, k-major smem) ----------------
template<int K, bool DOSP>
__device__ __forceinline__ void layer_col(const float* __restrict__ Wt,
                                          const float* __restrict__ bias,
                                          const float* in_s, float* out_s, int tid){
    float acc[16];
    float bv = bias[tid];
    #pragma unroll
    for(int r=0;r<16;r++) acc[r]=bv;
    #pragma unroll 4
    for(int c=0;c<K;c++){
        float w = Wt[c*HH+tid];
        const float4* p=(const float4*)&in_s[c*16];
        float4 v0=p[0],v1=p[1],v2=p[2],v3=p[3];
        acc[0]=fmaf(v0.x,w,acc[0]); acc[1]=fmaf(v0.y,w,acc[1]); acc[2]=fmaf(v0.z,w,acc[2]); acc[3]=fmaf(v0.w,w,acc[3]);
        acc[4]=fmaf(v1.x,w,acc[4]); acc[5]=fmaf(v1.y,w,acc[5]); acc[6]=fmaf(v1.z,w,acc[6]); acc[7]=fmaf(v1.w,w,acc[7]);
        acc[8]=fmaf(v2.x,w,acc[8]); acc[9]=fmaf(v2.y,w,acc[9]); acc[10]=fmaf(v2.z,w,acc[10]); acc[11]=fmaf(v2.w,w,acc[11]);
        acc[12]=fmaf(v3.x,w,acc[12]); acc[13]=fmaf(v3.y,w,acc[13]); acc[14]=fmaf(v3.z,w,acc[14]); acc[15]=fmaf(v3.w,w,acc[15]);
    }
    #pragma unroll
    for(int r=0;r<16;r++) out_s[tid*16+r] = DOSP ? splus_(acc[r]) : acc[r];
}

__device__ __forceinline__ void layer_out32(const float* __restrict__ Wt32,
                                            const float* __restrict__ bias,
                                            const float* in_s, float* out_s, int tid){
    #pragma unroll
    for(int rep=0;rep<2;rep++){
        int idx=rep*256+tid; int r=idx>>5, l=idx&31;
        float acc=bias[l];
        #pragma unroll 4
        for(int kk=0;kk<HH;kk++) acc = fmaf(in_s[kk*16+r], Wt32[kk*LL+l], acc);
        out_s[r*LL+l]=acc;
    }
}

// ---------------- one Euler step: fully fused f_net/h_net/g/update ----------------
__global__ void euler_kernel(int k, float* __restrict__ out, const float* __restrict__ dW,
                             const float* __restrict__ fb1,const float* __restrict__ fb2,const float* __restrict__ fb3,
                             const float* __restrict__ hb1,const float* __restrict__ hb2,const float* __restrict__ hb3,
                             const float* __restrict__ gW1,const float* __restrict__ gb1,
                             const float* __restrict__ gW2,const float* __restrict__ gb2){
    __shared__ float IN[96*16];    // [c][r] : rows 0..31 = z, 32..95 = ctx
    __shared__ float A1[HH*16];
    __shared__ float A2[HH*16];
    __shared__ float FV[16*LL], HVs[16*LL], GVs[16*LL];
    float* zs = out+1;
    int tid=threadIdx.x;           // 256
    int row0=blockIdx.x*16;        // 256 blocks

    for(int e=tid;e<16*LL;e+=256){int r=e>>5,l=e&31; int rid=row0+r;
        IN[l*16+r]=zs[((long)rid*TT+k)*LL+l];}
    for(int e=tid;e<16*CC;e+=256){int r=e>>6,c=e&63; int rid=row0+r; int b=rid&255;
        IN[(32+c)*16+r]=g_ctx[((k+1)*BB+b)*CC+c];}
    __syncthreads();

    layer_col<96,true >(g_fW1t, fb1, IN, A1, tid);  __syncthreads();
    layer_col<HH,true >(g_fW2t, fb2, A1, A2, tid);  __syncthreads();
    layer_out32(g_fW3t, fb3, A2, FV, tid);          __syncthreads();
    layer_col<LL,true >(g_hW1t, hb1, IN, A1, tid);  __syncthreads();
    layer_col<HH,true >(g_hW2t, hb2, A1, A2, tid);  __syncthreads();
    layer_out32(g_hW3t, hb3, A2, HVs, tid);         __syncthreads();

    // g_fn : per (r,l), 256 softplus terms
    #pragma unroll
    for(int rep=0;rep<2;rep++){
        int idx=rep*256+tid; int l=idx>>4, r=idx&15;
        float zl=IN[l*16+r];
        float acc=0.f;
        #pragma unroll 4
        for(int hh=0;hh<HH;hh++){
            float argv=fmaf(zl, gW1[l*HH+hh], gb1[l*HH+hh]);
            acc=fmaf(splus_(argv), gW2[l*HH+hh], acc);
        }
        GVs[r*LL+l] = sigm_(acc + gb2[l]) + 0.01f;
    }
    __syncthreads();

    // update + logqp increment
    #pragma unroll
    for(int rep=0;rep<2;rep++){
        int idx=rep*256+tid; int r=idx>>5,l=idx&31;
        int rid=row0+r;
        float z=IN[l*16+r];
        float fv=FV[r*LL+l], hv=HVs[r*LL+l], gv=GVs[r*LL+l];
        float u=(fv-hv)/gv;
        float dwv=dW[((long)k*SB + rid)*LL + l];
        float zn = z + fv*DTV + gv*(SQDT*dwv);
        zs[((long)rid*TT + k+1)*LL + l] = zn;
        float uu=u*u;
        #pragma unroll
        for(int off=16;off;off>>=1) uu += __shfl_down_sync(0xffffffffu, uu, off);
        if((tid&31)==0) g_logqp[rid] += 0.5f*uu*DTV;
    }
}

// ---------------- Poisson readout: accumulate sum of ell ----------------
__global__ void readout_kernel(const float* __restrict__ xs_pre, const float* __restrict__ C_out,
                               const float* __restrict__ d_out_v, const float* __restrict__ out){
    __shared__ float Cs[LL*DD];    // 16KB
    __shared__ float Zs[SS*LL];    // 2KB
    __shared__ float red[4];
    const float* zs = out+1;
    int blk=blockIdx.x; int t=blk>>8, b=blk&255;   // 32768 blocks
    int d=threadIdx.x;                              // 128
    for(int e=d;e<LL*DD;e+=128) Cs[e]=C_out[e];
    for(int e=d;e<SS*LL;e+=128){int s=e>>5,l=e&31;
        Zs[e]=zs[((long)(s*BB+b)*TT + t)*LL + l];}
    __syncthreads();
    float x = xs_pre[(b*TT+t)*DD+d];
    const float lut[5]={0.f,0.f,0.6931471805599453f,1.791759469228055f,3.1780538303479458f};
    int xi=(int)x;
    float lg = (xi>=0 && xi<5) ? lut[xi] : lgammaf(x+1.f);
    float base = d_out_v[d] + LOGDT;
    float acc=0.f;
    for(int s=0;s<SS;s++){
        float lr=base;
        #pragma unroll
        for(int l=0;l<LL;l++) lr = fmaf(Zs[s*LL+l], Cs[l*DD+d], lr);
        acc += x*lr - __expf(lr) - lg;
    }
    // block reduce (128 threads)
    #pragma unroll
    for(int off=16;off;off>>=1) acc += __shfl_down_sync(0xffffffffu, acc, off);
    if((d&31)==0) red[d>>5]=acc;
    __syncthreads();
    if(d==0){
        float s=red[0]+red[1]+red[2]+red[3];
        atomicAdd(&g_acc[0], (double)s);
    }
}

// ---------------- mean / unbiased variance over S ----------------
__global__ void meanvar_kernel(float* __restrict__ out){
    int idx=blockIdx.x*256+threadIdx.x;   // 1,048,576 = (b*T+t)*L+l
    if(idx>=BB*TT*LL) return;
    const float* zs=out+1;
    float v[SS];
    float sum=0.f;
    #pragma unroll
    for(int s=0;s<SS;s++){ v[s]=zs[(long)s*(BB*TT*LL)+idx]; sum+=v[s]; }
    float m=sum*(1.f/SS);
    float var=0.f;
    #pragma unroll
    for(int s=0;s<SS;s++){ float d=v[s]-m; var=fmaf(d,d,var); }
    var *= (1.f/(SS-1));
    out[1+(long)SS*BB*TT*LL + idx]=m;
    out[1+(long)SS*BB*TT*LL + BB*TT*LL + idx]=var;
}

// ---------------- final loss assembly ----------------
__global__ void final_kernel(float* __restrict__ out){
    __shared__ float red[256];
    int tid=threadIdx.x;
    float s=0.f;
    for(int i=tid;i<SB;i+=256) s+=g_logqp[i];
    red[tid]=s; __syncthreads();
    for(int st=128;st;st>>=1){ if(tid<st) red[tid]+=red[tid+st]; __syncthreads(); }
    if(tid==0){
        float log_pxs   = (float)(g_acc[0] / (double)(SS*BB));
        float logqp0    = (float)(g_acc[1] / (double)BB);
        float path      = red[0] / (float)(SS*BB);
        out[0] = -log_pxs + logqp0 + path;
    }
}

// ---------------- launch ----------------
extern "C" void kernel_launch(void* const* d_in, const int* in_sizes, int n_in,
                              void* d_out, int out_size){
    const float* xs_pre   =(const float*)d_in[0];
    const float* eps0     =(const float*)d_in[1];
    const float* dW       =(const float*)d_in[2];
    const float* gru_Wih  =(const float*)d_in[3];
    const float* gru_Whh  =(const float*)d_in[4];
    const float* gru_bih  =(const float*)d_in[5];
    const float* gru_bhh  =(const float*)d_in[6];
    const float* enc_W    =(const float*)d_in[7];
    const float* enc_b    =(const float*)d_in[8];
    const float* qz0_W    =(const float*)d_in[9];
    const float* qz0_b    =(const float*)d_in[10];
    const float* fW1      =(const float*)d_in[11];
    const float* fb1      =(const float*)d_in[12];
    const float* fW2      =(const float*)d_in[13];
    const float* fb2      =(const float*)d_in[14];
    const float* fW3      =(const float*)d_in[15];
    const float* fb3      =(const float*)d_in[16];
    const float* hW1      =(const float*)d_in[17];
    const float* hb1      =(const float*)d_in[18];
    const float* hW2      =(const float*)d_in[19];
    const float* hb2      =(const float*)d_in[20];
    const float* hW3      =(const float*)d_in[21];
    const float* hb3      =(const float*)d_in[22];
    const float* gW1      =(const float*)d_in[23];
    const float* gb1      =(const float*)d_in[24];
    const float* gW2      =(const float*)d_in[25];
    const float* gb2      =(const float*)d_in[26];
    const float* pz0_mean =(const float*)d_in[27];
    const float* pz0_logstd=(const float*)d_in[28];
    const float* C_out    =(const float*)d_in[29];
    const float* d_out_v  =(const float*)d_in[30];
    float* out=(float*)d_out;

    prep_kernel<<<256,256>>>(gru_Wih,gru_Whh,fW1,fW2,fW3,hW1,hW2,hW3,enc_W);
    gi_kernel<<<4096,256>>>(xs_pre, gru_bih);
    for(int t=0;t<TT;t++)
        gru_step_kernel<<<dim3(64,2),128>>>(t, gru_bhh);
    ctx_kernel<<<8192,256>>>(enc_b);
    z0_kernel<<<256,64>>>(eps0,qz0_W,qz0_b,pz0_mean,pz0_logstd,out);
    for(int k=0;k<TT-1;k++)
        euler_kernel<<<256,256>>>(k,out,dW,fb1,fb2,fb3,hb1,hb2,hb3,gW1,gb1,gW2,gb2);
    readout_kernel<<<32768,128>>>(xs_pre,C_out,d_out_v,out);
    meanvar_kernel<<<4096,256>>>(out);
    final_kernel<<<1,256>>>(out);
}

// round 3
// speedup vs baseline: 1.4402x; 1.4402x over previous
#include <cuda_runtime.h>
#include <cuda_bf16.h>
#include <math.h>

#define TT 128
#define BB 256
#define DD 128
#define LL 32
#define CC 64
#define HH 256
#define SS 16
#define SB 4096   // SS*BB

#define DTV 0.02f
#define SQDT 0.14142135623730951f     // sqrt(0.02)
#define LOGDT -3.9120230054281460f    // log(0.02)

typedef unsigned long long ull;

// ---------------- device scratch (static allocations only) ----------------
static __device__ float g_WihT[DD*768];
static __device__ float g_WhhT[HH*768];
static __device__ float g_fW1t[96*HH];
static __device__ float g_fW2t[HH*HH];
static __device__ float g_fW3t[HH*LL];
static __device__ float g_hW1t[LL*HH];
static __device__ float g_hW2t[HH*HH];
static __device__ float g_hW3t[HH*LL];
static __device__ float g_encWt[HH*CC];
static __device__ float g_gi[TT*BB*768];      // precomputed input gates (reversed time)
static __device__ float g_h[BB*HH];           // GRU hidden
static __device__ float g_hs[TT*BB*HH];       // all hidden states (reversed time)
static __device__ float g_ctx[TT*BB*CC];      // context, forward time (flip applied)
static __device__ float g_logqp[SB];          // per-(s,b) path logqp
static __device__ double g_acc[2];            // [0]=sum ell, [1]=sum kl0

__device__ __forceinline__ float sigm_(float x){ return 1.f/(1.f+__expf(-x)); }
__device__ __forceinline__ float splus_(float x){
    return fmaxf(x,0.f) + __logf(1.f+__expf(-fabsf(x)));
}
__device__ __forceinline__ ull pack2(float x, float y){
    ull r; asm("mov.b64 %0, {%1,%2};" : "=l"(r) : "f"(x), "f"(y)); return r;
}
__device__ __forceinline__ ull fma2(ull a, ull b, ull c){
    ull d; asm("fma.rn.f32x2 %0, %1, %2, %3;" : "=l"(d) : "l"(a), "l"(b), "l"(c)); return d;
}
__device__ __forceinline__ float2 unpack2(ull v){
    float2 f; asm("mov.b64 {%0,%1}, %2;" : "=f"(f.x), "=f"(f.y) : "l"(v)); return f;
}

// ---------------- prep: zero state + transpose weights ----------------
__global__ void prep_kernel(const float* __restrict__ Wih, const float* __restrict__ Whh,
                            const float* __restrict__ fW1, const float* __restrict__ fW2,
                            const float* __restrict__ fW3, const float* __restrict__ hW1,
                            const float* __restrict__ hW2, const float* __restrict__ hW3,
                            const float* __restrict__ encW){
    int i = blockIdx.x*blockDim.x + threadIdx.x;
    int nth = gridDim.x*blockDim.x;
    for (int k=i;k<BB*HH;k+=nth) g_h[k]=0.f;
    for (int k=i;k<SB;k+=nth)    g_logqp[k]=0.f;
    if (i<2) g_acc[i]=0.0;
    for (int k=i;k<768*DD;k+=nth){int n=k/DD,d=k%DD; g_WihT[d*768+n]=Wih[k];}
    for (int k=i;k<768*HH;k+=nth){int n=k/HH,d=k%HH; g_WhhT[d*768+n]=Whh[k];}
    for (int k=i;k<HH*96;k+=nth){int h=k/96,c=k%96;  g_fW1t[c*HH+h]=fW1[k];}
    for (int k=i;k<HH*HH;k+=nth){int h=k/HH,c=k%HH;  g_fW2t[c*HH+h]=fW2[k];}
    for (int k=i;k<LL*HH;k+=nth){int l=k/HH,c=k%HH;  g_fW3t[c*LL+l]=fW3[k];}
    for (int k=i;k<HH*LL;k+=nth){int h=k/LL,c=k%LL;  g_hW1t[c*HH+h]=hW1[k];}
    for (int k=i;k<HH*HH;k+=nth){int h=k/HH,c=k%HH;  g_hW2t[c*HH+h]=hW2[k];}
    for (int k=i;k<LL*HH;k+=nth){int l=k/HH,c=k%HH;  g_hW3t[c*LL+l]=hW3[k];}
    for (int k=i;k<CC*HH;k+=nth){int c2=k/HH,kk=k%HH;g_encWt[kk*CC+c2]=encW[k];}
}

// ---------------- gi = xs_rev @ WihT + bih  (one big GEMM) ----------------
__global__ void gi_kernel(const float* __restrict__ xs_pre, const float* __restrict__ bih){
    __shared__ float xT[DD*8];   // [k][i]
    int tid = threadIdx.x;       // 256
    int row0 = blockIdx.x*8;     // 4096 blocks
    for (int e=tid; e<8*DD; e+=256){
        int i=e>>7, k=e&127;
        int rid=row0+i; int t=rid>>8, b=rid&255;
        xT[k*8+i] = xs_pre[(b*TT + (TT-1-t))*DD + k];
    }
    __syncthreads();
    int n0=tid, n1=tid+256, n2=tid+512;
    float a0[8],a1[8],a2[8];
    float b0=bih[n0], b1=bih[n1], b2=bih[n2];
    #pragma unroll
    for(int i=0;i<8;i++){a0[i]=b0;a1[i]=b1;a2[i]=b2;}
    #pragma unroll 2
    for(int k=0;k<DD;k++){
        float w0=g_WihT[k*768+n0], w1=g_WihT[k*768+n1], w2=g_WihT[k*768+n2];
        float4 xa=*(const float4*)&xT[k*8], xb=*(const float4*)&xT[k*8+4];
        float xv[8]={xa.x,xa.y,xa.z,xa.w,xb.x,xb.y,xb.z,xb.w};
        #pragma unroll
        for(int i=0;i<8;i++){a0[i]=fmaf(xv[i],w0,a0[i]);a1[i]=fmaf(xv[i],w1,a1[i]);a2[i]=fmaf(xv[i],w2,a2[i]);}
    }
    for(int i=0;i<8;i++){
        int rid=row0+i;
        g_gi[rid*768+n0]=a0[i]; g_gi[rid*768+n1]=a1[i]; g_gi[rid*768+n2]=a2[i];
    }
}

// ---------------- one GRU step: 256 blocks x 384 threads, k-split 4, FFMA2 packed ----------------
__global__ __launch_bounds__(384) void gru_step2(int t, const float* __restrict__ bhh){
    __shared__ float hT[HH*8];        // [k][i]  8KB
    __shared__ float part[96*4*8];    // [(c*4+kp)][i]  12KB
    int tid = threadIdx.x;
    int bg = blockIdx.x>>3, hg = blockIdx.x&7;
    int b0 = bg*8, hbase = hg*32;
    for(int e=tid;e<8*HH;e+=384){ int i=e>>8, k=e&255; hT[k*8+i]=g_h[(b0+i)*HH+k]; }
    __syncthreads();
    int c  = tid%96;
    int kp = tid/96;                  // 0..3
    int gate = c>>5;
    int n = gate*256 + hbase + (c&31);
    int k0 = kp*64;
    ull acc0=0ull, acc1=0ull, acc2=0ull, acc3=0ull;
    const float* wcol = &g_WhhT[(long)k0*768 + n];
    #pragma unroll 4
    for(int kk=0;kk<64;kk++){
        float w = wcol[(long)kk*768];
        ull wp = pack2(w,w);
        const ull* hp = (const ull*)&hT[(k0+kk)*8];
        acc0=fma2(hp[0],wp,acc0); acc1=fma2(hp[1],wp,acc1);
        acc2=fma2(hp[2],wp,acc2); acc3=fma2(hp[3],wp,acc3);
    }
    float* pp = &part[(c*4+kp)*8];
    float2 v0=unpack2(acc0), v1=unpack2(acc1), v2=unpack2(acc2), v3=unpack2(acc3);
    pp[0]=v0.x; pp[1]=v0.y; pp[2]=v1.x; pp[3]=v1.y;
    pp[4]=v2.x; pp[5]=v2.y; pp[6]=v3.x; pp[7]=v3.y;
    __syncthreads();
    if(tid<256){
        int b = tid>>5, hhl = tid&31;
        int h = hbase + hhl;
        float dr=bhh[h], dz=bhh[256+h], dn=bhh[512+h];
        #pragma unroll
        for(int q=0;q<4;q++){
            dr += part[(((0*32+hhl)*4)+q)*8 + b];
            dz += part[(((1*32+hhl)*4)+q)*8 + b];
            dn += part[(((2*32+hhl)*4)+q)*8 + b];
        }
        long gbase = (long)(t*BB + b0+b)*768;
        float gr=g_gi[gbase+h], gz=g_gi[gbase+256+h], gn=g_gi[gbase+512+h];
        float r_ = sigm_(gr+dr);
        float u  = sigm_(gz+dz);
        float nn = tanhf(gn + r_*dn);
        float hp_ = hT[h*8+b];
        float hnw = (1.f-u)*nn + u*hp_;
        g_h[(b0+b)*HH+h] = hnw;
        g_hs[((long)t*BB + b0+b)*HH + h] = hnw;
    }
}

// ---------------- ctx = hs @ encWt + enc_b, flipped to forward time ----------------
__global__ void ctx_kernel(const float* __restrict__ enc_b){
    __shared__ float hT[HH*4];
    int tid=threadIdx.x;             // 256
    int row0=blockIdx.x*4;           // 8192 blocks
    for(int e=tid;e<4*HH;e+=256){int i=e>>8,k=e&255; hT[k*4+i]=g_hs[(row0+i)*HH+k];}
    __syncthreads();
    int i=tid>>6, c=tid&63;
    float acc=enc_b[c];
    #pragma unroll 4
    for(int k=0;k<HH;k++) acc = fmaf(hT[k*4+i], g_encWt[k*CC+c], acc);
    int rid=row0+i; int tr=rid>>8, b=rid&255;
    g_ctx[((TT-1-tr)*BB + b)*CC + c] = acc;
}

// ---------------- z0 + KL(q||p) ----------------
__global__ void z0_kernel(const float* __restrict__ eps0, const float* __restrict__ qz0_W,
                          const float* __restrict__ qz0_b, const float* __restrict__ pz0_mean,
                          const float* __restrict__ pz0_logstd, float* __restrict__ out){
    int b = blockIdx.x;      // 256
    int tid = threadIdx.x;   // 64
    __shared__ float c0[64]; __shared__ float q[64];
    c0[tid] = g_ctx[b*CC + tid];
    __syncthreads();
    float acc = qz0_b[tid];
    for(int c=0;c<CC;c++) acc = fmaf(c0[c], qz0_W[tid*CC+c], acc);
    q[tid]=acc;
    __syncthreads();
    if(tid<32){
        float qm=q[tid], ql=q[32+tid];
        float pm=pz0_mean[tid], pl=pz0_logstd[tid];
        float kl = pl - ql + (expf(2.f*ql) + (qm-pm)*(qm-pm))/(2.f*expf(2.f*pl)) - 0.5f;
        #pragma unroll
        for(int off=16;off;off>>=1) kl += __shfl_down_sync(0xffffffffu, kl, off);
        if(tid==0) atomicAdd(&g_acc[1], (double)kl);
    }
    float* zs = out+1;
    for(int e=tid;e<SS*LL;e+=64){
        int s=e>>5, l=e&31;
        float val = q[l] + expf(q[32+l]) * eps0[(s*BB+b)*LL + l];
        zs[((long)(s*BB+b)*TT + 0)*LL + l] = val;
    }
}

// ---------------- packed MLP layer (column-parallel, k-major smem) ----------------
template<int K, bool DOSP>
__device__ __forceinline__ void layer_colp(const float* __restrict__ Wt,
                                           const float* __restrict__ bias,
                                           const float* in_s, float* out_s, int tid){
    float bv = bias[tid];
    ull bp = pack2(bv,bv);
    ull acc[8];
    #pragma unroll
    for(int r=0;r<8;r++) acc[r]=bp;
    #pragma unroll 4
    for(int c=0;c<K;c++){
        float w = Wt[c*HH+tid];
        ull wp = pack2(w,w);
        const ull* p = (const ull*)&in_s[c*16];
        #pragma unroll
        for(int r=0;r<8;r++) acc[r]=fma2(p[r],wp,acc[r]);
    }
    #pragma unroll
    for(int r=0;r<8;r++){
        float2 v=unpack2(acc[r]);
        out_s[tid*16+2*r  ] = DOSP ? splus_(v.x) : v.x;
        out_s[tid*16+2*r+1] = DOSP ? splus_(v.y) : v.y;
    }
}

__device__ __forceinline__ void layer_out32p(const float* __restrict__ Wt32,
                                             const float* __restrict__ bias,
                                             const float* in_s, float* out_s, int tid){
    int l = tid&31, rp = tid>>5;   // rp 0..7 -> rows 2rp, 2rp+1
    float bv = bias[l];
    ull acc = pack2(bv,bv);
    #pragma unroll 4
    for(int kk=0;kk<HH;kk++){
        ull zp = *(const ull*)&in_s[kk*16 + 2*rp];
        float w = Wt32[kk*LL+l];
        acc = fma2(zp, pack2(w,w), acc);
    }
    float2 v = unpack2(acc);
    out_s[(2*rp  )*LL + l] = v.x;
    out_s[(2*rp+1)*LL + l] = v.y;
}

// ---------------- ALL Euler steps in one kernel: z in smem, g weights in smem ----------------
__global__ __launch_bounds__(256,2) void euler_all_kernel(
        float* __restrict__ out, const float* __restrict__ dW,
        const float* __restrict__ fb1,const float* __restrict__ fb2,const float* __restrict__ fb3,
        const float* __restrict__ hb1,const float* __restrict__ hb2,const float* __restrict__ hb3,
        const float* __restrict__ gW1,const float* __restrict__ gb1,
        const float* __restrict__ gW2,const float* __restrict__ gb2){
    extern __shared__ float sm[];
    float* IN   = sm;            // 96*16  = 1536
    float* A1   = IN  + 1536;    // 256*16 = 4096
    float* A2   = A1  + 4096;    // 4096
    float* FV   = A2  + 4096;    // 16*32 [r*32+l] = 512
    float* HV   = FV  + 512;     // 512
    float* GV   = HV  + 512;     // 512
    float* GW1s = GV  + 512;     // 32*256 = 8192
    float* GB1s = GW1s+ 8192;    // 8192
    float* LQ   = GB1s+ 8192;    // 16
    int tid = threadIdx.x;       // 256
    int row0 = blockIdx.x*16;    // 256 blocks
    float* zs = out+1;

    for(int e=tid;e<LL*HH;e+=256){ GW1s[e]=gW1[e]; GB1s[e]=gb1[e]; }
    if(tid<16) LQ[tid]=0.f;
    for(int e=tid;e<16*LL;e+=256){ int r=e>>5,l=e&31;
        IN[l*16+r]=zs[((long)(row0+r)*TT)*LL+l]; }

    for(int k=0;k<TT-1;k++){
        for(int e=tid;e<16*CC;e+=256){ int r=e>>6,c=e&63; int b=(row0+r)&255;
            IN[(32+c)*16+r]=g_ctx[((k+1)*BB+b)*CC+c]; }
        __syncthreads();

        layer_colp<96,true>(g_fW1t, fb1, IN, A1, tid);  __syncthreads();
        layer_colp<HH,true>(g_fW2t, fb2, A1, A2, tid);  __syncthreads();
        layer_out32p(g_fW3t, fb3, A2, FV, tid);         __syncthreads();
        layer_colp<LL,true>(g_hW1t, hb1, IN, A1, tid);  __syncthreads();
        layer_colp<HH,true>(g_hW2t, hb2, A1, A2, tid);  __syncthreads();
        layer_out32p(g_hW3t, hb3, A2, HV, tid);

        // g_fn (MUFU-heavy): weights from smem
        #pragma unroll
        for(int rep=0;rep<2;rep++){
            int idx=rep*256+tid; int l=idx>>4, r=idx&15;
            float zl=IN[l*16+r];
            float acc=0.f;
            #pragma unroll 4
            for(int hh2=0;hh2<HH;hh2++){
                float a = fmaf(zl, GW1s[l*HH+hh2], GB1s[l*HH+hh2]);
                acc = fmaf(splus_(a), gW2[l*HH+hh2], acc);
            }
            GV[r*LL+l] = sigm_(acc + gb2[l]) + 0.01f;
        }
        __syncthreads();

        // update + logqp
        #pragma unroll
        for(int rep=0;rep<2;rep++){
            int idx=rep*256+tid; int r=idx>>5, l=idx&31;
            int rid=row0+r;
            float z=IN[l*16+r];
            float fv=FV[r*LL+l], hv=HV[r*LL+l], gv=GV[r*LL+l];
            float u2=(fv-hv)/gv;
            float dwv=__ldg(&dW[((long)k*SB+rid)*LL+l]);
            float zn = z + fv*DTV + gv*(SQDT*dwv);
            IN[l*16+r]=zn;
            zs[((long)rid*TT + k+1)*LL + l]=zn;
            float uu=u2*u2;
            #pragma unroll
            for(int off=16;off;off>>=1) uu += __shfl_down_sync(0xffffffffu, uu, off);
            if((tid&31)==0) LQ[r] += 0.5f*uu*DTV;
        }
        __syncthreads();
    }
    if(tid<16) g_logqp[row0+tid]=LQ[tid];
}

// ---------------- Poisson readout: accumulate sum of ell ----------------
__global__ void readout_kernel(const float* __restrict__ xs_pre, const float* __restrict__ C_out,
                               const float* __restrict__ d_out_v, const float* __restrict__ out){
    __shared__ float Cs[LL*DD];    // 16KB
    __shared__ float Zs[SS*LL];    // 2KB
    __shared__ float red[4];
    const float* zs = out+1;
    int blk=blockIdx.x; int t=blk>>8, b=blk&255;   // 32768 blocks
    int d=threadIdx.x;                              // 128
    for(int e=d;e<LL*DD;e+=128) Cs[e]=C_out[e];
    for(int e=d;e<SS*LL;e+=128){int s=e>>5,l=e&31;
        Zs[e]=zs[((long)(s*BB+b)*TT + t)*LL + l];}
    __syncthreads();
    float x = xs_pre[(b*TT+t)*DD+d];
    const float lut[5]={0.f,0.f,0.6931471805599453f,1.791759469228055f,3.1780538303479458f};
    int xi=(int)x;
    float lg = (xi>=0 && xi<5) ? lut[xi] : lgammaf(x+1.f);
    float base = d_out_v[d] + LOGDT;
    float acc=0.f;
    for(int s=0;s<SS;s++){
        float lr=base;
        #pragma unroll
        for(int l=0;l<LL;l++) lr = fmaf(Zs[s*LL+l], Cs[l*DD+d], lr);
        acc += x*lr - __expf(lr) - lg;
    }
    #pragma unroll
    for(int off=16;off;off>>=1) acc += __shfl_down_sync(0xffffffffu, acc, off);
    if((d&31)==0) red[d>>5]=acc;
    __syncthreads();
    if(d==0){
        float s=red[0]+red[1]+red[2]+red[3];
        atomicAdd(&g_acc[0], (double)s);
    }
}

// ---------------- mean / unbiased variance over S ----------------
__global__ void meanvar_kernel(float* __restrict__ out){
    int idx=blockIdx.x*256+threadIdx.x;
    if(idx>=BB*TT*LL) return;
    const float* zs=out+1;
    float v[SS];
    float sum=0.f;
    #pragma unroll
    for(int s=0;s<SS;s++){ v[s]=zs[(long)s*(BB*TT*LL)+idx]; sum+=v[s]; }
    float m=sum*(1.f/SS);
    float var=0.f;
    #pragma unroll
    for(int s=0;s<SS;s++){ float d=v[s]-m; var=fmaf(d,d,var); }
    var *= (1.f/(SS-1));
    out[1+(long)SS*BB*TT*LL + idx]=m;
    out[1+(long)SS*BB*TT*LL + BB*TT*LL + idx]=var;
}

// ---------------- final loss assembly ----------------
__global__ void final_kernel(float* __restrict__ out){
    __shared__ float red[256];
    int tid=threadIdx.x;
    float s=0.f;
    for(int i=tid;i<SB;i+=256) s+=g_logqp[i];
    red[tid]=s; __syncthreads();
    for(int st=128;st;st>>=1){ if(tid<st) red[tid]+=red[tid+st]; __syncthreads(); }
    if(tid==0){
        float log_pxs   = (float)(g_acc[0] / (double)(SS*BB));
        float logqp0    = (float)(g_acc[1] / (double)BB);
        float path      = red[0] / (float)(SS*BB);
        out[0] = -log_pxs + logqp0 + path;
    }
}

// ---------------- launch ----------------
extern "C" void kernel_launch(void* const* d_in, const int* in_sizes, int n_in,
                              void* d_out, int out_size){
    const float* xs_pre   =(const float*)d_in[0];
    const float* eps0     =(const float*)d_in[1];
    const float* dW       =(const float*)d_in[2];
    const float* gru_Wih  =(const float*)d_in[3];
    const float* gru_Whh  =(const float*)d_in[4];
    const float* gru_bih  =(const float*)d_in[5];
    const float* gru_bhh  =(const float*)d_in[6];
    const float* enc_W    =(const float*)d_in[7];
    const float* enc_b    =(const float*)d_in[8];
    const float* qz0_W    =(const float*)d_in[9];
    const float* qz0_b    =(const float*)d_in[10];
    const float* fW1      =(const float*)d_in[11];
    const float* fb1      =(const float*)d_in[12];
    const float* fW2      =(const float*)d_in[13];
    const float* fb2      =(const float*)d_in[14];
    const float* fW3      =(const float*)d_in[15];
    const float* fb3      =(const float*)d_in[16];
    const float* hW1      =(const float*)d_in[17];
    const float* hb1      =(const float*)d_in[18];
    const float* hW2      =(const float*)d_in[19];
    const float* hb2      =(const float*)d_in[20];
    const float* hW3      =(const float*)d_in[21];
    const float* hb3      =(const float*)d_in[22];
    const float* gW1      =(const float*)d_in[23];
    const float* gb1      =(const float*)d_in[24];
    const float* gW2      =(const float*)d_in[25];
    const float* gb2      =(const float*)d_in[26];
    const float* pz0_mean =(const float*)d_in[27];
    const float* pz0_logstd=(const float*)d_in[28];
    const float* C_out    =(const float*)d_in[29];
    const float* d_out_v  =(const float*)d_in[30];
    float* out=(float*)d_out;

    static int smem_set = 0;
    const int EULER_SMEM = (1536+4096+4096+512+512+512+8192+8192+16)*4;
    if(!smem_set){
        cudaFuncSetAttribute(euler_all_kernel,
                             cudaFuncAttributeMaxDynamicSharedMemorySize, EULER_SMEM);
        smem_set = 1;
    }

    prep_kernel<<<256,256>>>(gru_Wih,gru_Whh,fW1,fW2,fW3,hW1,hW2,hW3,enc_W);
    gi_kernel<<<4096,256>>>(xs_pre, gru_bih);
    for(int t=0;t<TT;t++)
        gru_step2<<<256,384>>>(t, gru_bhh);
    ctx_kernel<<<8192,256>>>(enc_b);
    z0_kernel<<<256,64>>>(eps0,qz0_W,qz0_b,pz0_mean,pz0_logstd,out);
    euler_all_kernel<<<256,256,EULER_SMEM>>>(out,dW,fb1,fb2,fb3,hb1,hb2,hb3,gW1,gb1,gW2,gb2);
    readout_kernel<<<32768,128>>>(xs_pre,C_out,d_out_v,out);
    meanvar_kernel<<<4096,256>>>(out);
    final_kernel<<<1,256>>>(out);
}